// round 2
// baseline (speedup 1.0000x reference)
#include <cuda_runtime.h>

#define HDIM 16
#define UDIM 7
#define HID  64
#define XDIM 23   // HDIM + UDIM

typedef unsigned long long ull;

__device__ __forceinline__ ull pack2(float lo, float hi) {
    ull r; asm("mov.b64 %0, {%1,%2};" : "=l"(r) : "f"(lo), "f"(hi)); return r;
}
__device__ __forceinline__ float2 unpack2(ull v) {
    float2 f; asm("mov.b64 {%0,%1}, %2;" : "=f"(f.x), "=f"(f.y) : "l"(v)); return f;
}
// Packed dual-fp32 FMA (sm_100+): two fp32 MACs per instruction, full precision.
__device__ __forceinline__ ull fma2(ull a, ull b, ull c) {
    ull d; asm("fma.rn.f32x2 %0, %1, %2, %3;" : "=l"(d) : "l"(a), "l"(b), "l"(c)); return d;
}
// tanh(x) = (e - 1)/(e + 1), e = exp(2x), via MUFU.EX2 + MUFU.RCP. ~1e-6 abs err.
__device__ __forceinline__ float fast_tanh(float x) {
    float xc = fminf(fmaxf(x, -15.0f), 15.0f);   // avoid inf*0 -> NaN
    float e;
    asm("ex2.approx.f32 %0, %1;" : "=f"(e) : "f"(xc * 2.8853900817779268f)); // 2*log2(e)
    float r;
    asm("rcp.approx.f32 %0, %1;" : "=f"(r) : "f"(e + 1.0f));
    return (e - 1.0f) * r;
}

__global__ __launch_bounds__(64, 1)
void node_scan_kernel(const float* __restrict__ U,
                      const float* __restrict__ W1, const float* __restrict__ b1,
                      const float* __restrict__ W2, const float* __restrict__ b2,
                      const float* __restrict__ W3, const float* __restrict__ b3,
                      const float* __restrict__ wd, const float* __restrict__ bd,
                      const float* __restrict__ wt, const float* __restrict__ bt,
                      const float* __restrict__ wc, const float* __restrict__ bc,
                      const float* __restrict__ h0,
                      float* __restrict__ out, int T)
{
    __shared__ __align__(16) float sx[24];    // x = [h(16), u(7)], sx[23]=0 pad
    __shared__ __align__(16) float sz1[64];
    __shared__ __align__(16) float sz2[64];

    const int tid = threadIdx.x;
    const float dt = (float)(5.0 / 60.0);

    // ---- per-thread weights, packed into f32x2 registers ----
    ull w1p[12];
    #pragma unroll
    for (int j = 0; j < 11; ++j)
        w1p[j] = pack2(W1[tid * XDIM + 2 * j], W1[tid * XDIM + 2 * j + 1]);
    w1p[11] = pack2(W1[tid * XDIM + 22], 0.0f);   // pad col 23 with 0
    const float b1r = b1[tid];

    ull w2p[32];
    #pragma unroll
    for (int j = 0; j < 32; ++j)
        w2p[j] = pack2(W2[tid * HID + 2 * j], W2[tid * HID + 2 * j + 1]);
    const float b2r = b2[tid];

    // warp0: W3 split — lane = (row r3, col-half cb)
    const int r3 = tid & 15;
    const int cb = (tid & 16) * 2;                 // 0 or 32
    ull w3p[16];
    float b3r = 0.0f;
    if (tid < 32) {
        #pragma unroll
        for (int j = 0; j < 16; ++j)
            w3p[j] = pack2(W3[r3 * HID + cb + 2 * j], W3[r3 * HID + cb + 2 * j + 1]);
        b3r = b3[r3];
    }

    // warp1 lanes 0..2: readout weights (wd/wt/wc) packed
    ull rwp[8];
    float rb = 0.0f;
    if (tid >= 32) {
        const int k = tid - 32;
        const float* rw = (k == 1) ? wt : (k == 2) ? wc : wd;
        if (k == 0) rb = bd[0];
        else if (k == 1) rb = bt[0];
        else if (k == 2) rb = bc[0];
        #pragma unroll
        for (int j = 0; j < 8; ++j)
            rwp[j] = pack2(rw[2 * j], rw[2 * j + 1]);
    }

    if (tid < 16) sx[tid] = h0[tid];
    if (tid == 0) sx[23] = 0.0f;

    float ureg = (tid < UDIM) ? U[tid] : 0.0f;     // prefetch u_0

    const ulonglong2* sxv  = (const ulonglong2*)sx;
    const ulonglong2* sz1v = (const ulonglong2*)sz1;
    const ulonglong2* sz2v = (const ulonglong2*)sz2;

    float* outp = out + (size_t)(tid & 31) * (size_t)T;   // row base for warp1 lanes 0..2

    for (int t = 0; t < T; ++t) {
        if (tid < UDIM) sx[HDIM + tid] = ureg;
        __syncthreads();                           // B1: [h_t, u_t] visible

        // prefetch u_{t+1} (latency hidden by step body)
        if (tid < UDIM && (t + 1) < T) ureg = U[(t + 1) * UDIM + tid];

        // warp1: snapshot h_t into registers (readouts run after B3, race-free)
        ull hsn[8];
        if (tid >= 32) {
            #pragma unroll
            for (int q = 0; q < 4; ++q) {
                ulonglong2 v = sxv[q];
                hsn[2 * q] = v.x; hsn[2 * q + 1] = v.y;
            }
        }

        // ---- layer 1: z1 = tanh(W1 x + b1), one row per thread (12 FMA2) ----
        {
            ull a0 = pack2(b1r, 0.0f), a1 = pack2(0.0f, 0.0f);
            #pragma unroll
            for (int q = 0; q < 6; ++q) {
                ulonglong2 v = sxv[q];
                a0 = fma2(w1p[2 * q], v.x, a0);
                a1 = fma2(w1p[2 * q + 1], v.y, a1);
            }
            float2 f0 = unpack2(a0), f1 = unpack2(a1);
            sz1[tid] = fast_tanh((f0.x + f0.y) + (f1.x + f1.y));
        }
        __syncthreads();                           // B2: z1 ready

        // ---- layer 2: z2 = tanh(W2 z1 + b2), one row per thread (32 FMA2) ----
        {
            ull a0 = pack2(b2r, 0.0f), a1 = pack2(0.0f, 0.0f);
            ull a2 = pack2(0.0f, 0.0f), a3 = pack2(0.0f, 0.0f);
            #pragma unroll
            for (int q = 0; q < 16; ++q) {
                ulonglong2 v = sz1v[q];
                if ((q & 1) == 0) {
                    a0 = fma2(w2p[2 * q], v.x, a0);
                    a1 = fma2(w2p[2 * q + 1], v.y, a1);
                } else {
                    a2 = fma2(w2p[2 * q], v.x, a2);
                    a3 = fma2(w2p[2 * q + 1], v.y, a3);
                }
            }
            float2 f0 = unpack2(a0), f1 = unpack2(a1);
            float2 f2 = unpack2(a2), f3 = unpack2(a3);
            float s = ((f0.x + f0.y) + (f1.x + f1.y)) + ((f2.x + f2.y) + (f3.x + f3.y));
            sz2[tid] = fast_tanh(s);
        }
        __syncthreads();                           // B3: z2 ready

        if (tid < 32) {
            // ---- layer 3: dh row r3, 32 cols per lane (16 FMA2), halves joined by shfl ----
            const int q0 = cb >> 2;                // ulonglong2 offset: 0 or 8
            ull a0 = pack2(0.0f, 0.0f), a1 = pack2(0.0f, 0.0f);
            #pragma unroll
            for (int q = 0; q < 8; ++q) {
                ulonglong2 v = sz2v[q0 + q];
                a0 = fma2(w3p[2 * q], v.x, a0);
                a1 = fma2(w3p[2 * q + 1], v.y, a1);
            }
            float2 f0 = unpack2(a0), f1 = unpack2(a1);
            float pr = (f0.x + f0.y) + (f1.x + f1.y);
            float prx = __shfl_xor_sync(0xffffffffu, pr, 16);
            if (tid < 16) {
                float dh = pr + prx + b3r;
                sx[tid] = fmaf(dt, dh, sx[tid]);   // Euler update
            }
        } else {
            // ---- readouts on h_t snapshot (8 FMA2 per lane, lanes 0..2 of warp1) ----
            ull a0 = pack2(rb, 0.0f), a1 = pack2(0.0f, 0.0f);
            #pragma unroll
            for (int j = 0; j < 4; ++j) {
                a0 = fma2(rwp[2 * j], hsn[2 * j], a0);
                a1 = fma2(rwp[2 * j + 1], hsn[2 * j + 1], a1);
            }
            float2 f0 = unpack2(a0), f1 = unpack2(a1);
            float acc = (f0.x + f0.y) + (f1.x + f1.y);
            if (tid < 35) outp[t] = acc;
        }
        // next iteration's B1 publishes the new h
    }

    __syncthreads();
    if (tid < HDIM) out[(size_t)3 * (size_t)T + tid] = sx[tid];
}

extern "C" void kernel_launch(void* const* d_in, const int* in_sizes, int n_in,
                              void* d_out, int out_size)
{
    const float* U  = (const float*)d_in[0];
    const float* W1 = (const float*)d_in[1];
    const float* b1 = (const float*)d_in[2];
    const float* W2 = (const float*)d_in[3];
    const float* b2 = (const float*)d_in[4];
    const float* W3 = (const float*)d_in[5];
    const float* b3 = (const float*)d_in[6];
    const float* wd = (const float*)d_in[7];
    const float* bd = (const float*)d_in[8];
    const float* wt = (const float*)d_in[9];
    const float* bt = (const float*)d_in[10];
    const float* wc = (const float*)d_in[11];
    const float* bc = (const float*)d_in[12];
    const float* h0 = (const float*)d_in[13];
    float* out = (float*)d_out;

    const int T = in_sizes[0] / UDIM;

    node_scan_kernel<<<1, 64>>>(U, W1, b1, W2, b2, W3, b3,
                                wd, bd, wt, bt, wc, bc, h0, out, T);
}

// round 4
// speedup vs baseline: 1.6613x; 1.6613x over previous
#include <cuda_runtime.h>

#define HDIM 16
#define UDIM 7
#define HID  64
#define XDIM 23   // HDIM + UDIM

// tanh(x) = (e - 1)/(e + 1), e = exp(2x), via MUFU.EX2 + MUFU.RCP. ~1e-6 abs err.
__device__ __forceinline__ float fast_tanh(float x) {
    float xc = fminf(fmaxf(x, -15.0f), 15.0f);   // avoid inf*0 -> NaN
    float e;
    asm("ex2.approx.f32 %0, %1;" : "=f"(e) : "f"(xc * 2.8853900817779268f)); // 2*log2(e)
    float r;
    asm("rcp.approx.f32 %0, %1;" : "=f"(r) : "f"(e + 1.0f));
    return (e - 1.0f) * r;
}

__global__ __launch_bounds__(64, 1)
void node_scan_kernel(const float* __restrict__ U,
                      const float* __restrict__ W1, const float* __restrict__ b1,
                      const float* __restrict__ W2, const float* __restrict__ b2,
                      const float* __restrict__ W3, const float* __restrict__ b3,
                      const float* __restrict__ wd, const float* __restrict__ bd,
                      const float* __restrict__ wt, const float* __restrict__ bt,
                      const float* __restrict__ wc, const float* __restrict__ bc,
                      const float* __restrict__ h0,
                      float* __restrict__ out, int T)
{
    __shared__ __align__(16) float sx[24];    // x = [h(16), u(7)], sx[23]=0 pad
    __shared__ __align__(16) float sz1[64];
    __shared__ __align__(16) float sz2[64];

    const int tid = threadIdx.x;
    const float dt = (float)(5.0 / 60.0);

    // ---- per-thread weights in registers ----
    float w1r[24];
    #pragma unroll
    for (int j = 0; j < XDIM; ++j) w1r[j] = W1[tid * XDIM + j];
    w1r[23] = 0.0f;
    const float b1r = b1[tid];

    float w2r[64];
    #pragma unroll
    for (int j = 0; j < HID; ++j) w2r[j] = W2[tid * HID + j];
    const float b2r = b2[tid];

    // warp0: W3 split — lane = (row r3, col-half cb); halves joined by shfl_xor(16)
    const int r3 = tid & 15;
    const int cb = (tid & 16) * 2;                 // 0 or 32
    float w3r[32];
    float b3r = 0.0f;
    if (tid < 32) {
        #pragma unroll
        for (int j = 0; j < 32; ++j) w3r[j] = W3[r3 * HID + cb + j];
        b3r = b3[r3];
    }

    // warp1 lanes 0..2: readout weights (wd/wt/wc) in registers
    float rwr[16];
    float rb = 0.0f;
    if (tid >= 32 && tid < 35) {
        const int k = tid - 32;
        const float* rw = (k == 1) ? wt : (k == 2) ? wc : wd;
        rb = (k == 0) ? bd[0] : (k == 1) ? bt[0] : bc[0];
        #pragma unroll
        for (int j = 0; j < HDIM; ++j) rwr[j] = rw[j];
    }

    if (tid < 16) sx[tid] = h0[tid];
    if (tid == 0) sx[23] = 0.0f;

    float ureg = (tid < UDIM) ? U[tid] : 0.0f;     // prefetch u_0

    const float4* sxv  = (const float4*)sx;
    const float4* sz1v = (const float4*)sz1;
    const float4* sz2v = (const float4*)sz2;

    float* outp = out + (size_t)(tid & 31) * (size_t)T;  // row base, warp1 lanes 0..2

    for (int t = 0; t < T; ++t) {
        if (tid < UDIM) sx[HDIM + tid] = ureg;
        __syncthreads();                           // B1: [h_t, u_t] visible

        // prefetch u_{t+1} (latency hidden by step body)
        if (tid < UDIM && (t + 1) < T) ureg = U[(t + 1) * UDIM + tid];

        // warp1: snapshot h_t (readouts run later, race-free vs the h-update)
        float hsn[16];
        if (tid >= 32) {
            #pragma unroll
            for (int q = 0; q < 4; ++q) {
                float4 v = sxv[q];
                hsn[4 * q + 0] = v.x; hsn[4 * q + 1] = v.y;
                hsn[4 * q + 2] = v.z; hsn[4 * q + 3] = v.w;
            }
        }

        // ---- layer 1: z1 = tanh(W1 x + b1), one row per thread ----
        {
            float a0 = b1r, a1 = 0.f, a2 = 0.f, a3 = 0.f;
            #pragma unroll
            for (int q = 0; q < 6; ++q) {
                float4 v = sxv[q];
                a0 = fmaf(w1r[4 * q + 0], v.x, a0);
                a1 = fmaf(w1r[4 * q + 1], v.y, a1);
                a2 = fmaf(w1r[4 * q + 2], v.z, a2);
                a3 = fmaf(w1r[4 * q + 3], v.w, a3);
            }
            sz1[tid] = fast_tanh((a0 + a1) + (a2 + a3));
        }
        __syncthreads();                           // B2: z1 ready

        // ---- layer 2: z2 = tanh(W2 z1 + b2), one row per thread ----
        {
            float a0 = b2r, a1 = 0.f, a2 = 0.f, a3 = 0.f;
            #pragma unroll
            for (int q = 0; q < 16; ++q) {
                float4 v = sz1v[q];
                a0 = fmaf(w2r[4 * q + 0], v.x, a0);
                a1 = fmaf(w2r[4 * q + 1], v.y, a1);
                a2 = fmaf(w2r[4 * q + 2], v.z, a2);
                a3 = fmaf(w2r[4 * q + 3], v.w, a3);
            }
            sz2[tid] = fast_tanh((a0 + a1) + (a2 + a3));
        }
        __syncthreads();                           // B3: z2 ready

        if (tid < 32) {
            // ---- layer 3: dh row r3, 32 cols per lane; halves joined by shfl ----
            const int q0 = cb >> 2;                // float4 offset: 0 or 8
            float c0 = 0.f, c1 = 0.f, c2 = 0.f, c3 = 0.f;
            #pragma unroll
            for (int q = 0; q < 8; ++q) {
                float4 v = sz2v[q0 + q];
                c0 = fmaf(w3r[4 * q + 0], v.x, c0);
                c1 = fmaf(w3r[4 * q + 1], v.y, c1);
                c2 = fmaf(w3r[4 * q + 2], v.z, c2);
                c3 = fmaf(w3r[4 * q + 3], v.w, c3);
            }
            float pr = (c0 + c1) + (c2 + c3);
            float prx = __shfl_xor_sync(0xffffffffu, pr, 16);
            if (tid < 16) {
                float dh = pr + prx + b3r;
                sx[tid] = fmaf(dt, dh, sx[tid]);   // Euler update
            }
        } else if (tid < 35) {
            // ---- readouts on h_t snapshot ----
            float a0 = rb, a1 = 0.f, a2 = 0.f, a3 = 0.f;
            #pragma unroll
            for (int j = 0; j < 4; ++j) {
                a0 = fmaf(rwr[4 * j + 0], hsn[4 * j + 0], a0);
                a1 = fmaf(rwr[4 * j + 1], hsn[4 * j + 1], a1);
                a2 = fmaf(rwr[4 * j + 2], hsn[4 * j + 2], a2);
                a3 = fmaf(rwr[4 * j + 3], hsn[4 * j + 3], a3);
            }
            outp[t] = (a0 + a1) + (a2 + a3);
        }
        // next iteration's B1 publishes the new h
    }

    __syncthreads();
    if (tid < HDIM) out[(size_t)3 * (size_t)T + tid] = sx[tid];
}

extern "C" void kernel_launch(void* const* d_in, const int* in_sizes, int n_in,
                              void* d_out, int out_size)
{
    const float* U  = (const float*)d_in[0];
    const float* W1 = (const float*)d_in[1];
    const float* b1 = (const float*)d_in[2];
    const float* W2 = (const float*)d_in[3];
    const float* b2 = (const float*)d_in[4];
    const float* W3 = (const float*)d_in[5];
    const float* b3 = (const float*)d_in[6];
    const float* wd = (const float*)d_in[7];
    const float* bd = (const float*)d_in[8];
    const float* wt = (const float*)d_in[9];
    const float* bt = (const float*)d_in[10];
    const float* wc = (const float*)d_in[11];
    const float* bc = (const float*)d_in[12];
    const float* h0 = (const float*)d_in[13];
    float* out = (float*)d_out;

    const int T = in_sizes[0] / UDIM;

    node_scan_kernel<<<1, 64>>>(U, W1, b1, W2, b2, W3, b3,
                                wd, bd, wt, bt, wc, bc, h0, out, T);
}